// round 4
// baseline (speedup 1.0000x reference)
#include <cuda_runtime.h>
#include <cstdint>

#define T_ 512
#define F_ 24
#define H_ 12

typedef unsigned long long u64;

// ---- f32x2 packed helpers (sm_103a) ----
__device__ __forceinline__ u64 pk2(float lo, float hi) {
    u64 r; asm("mov.b64 %0,{%1,%2};" : "=l"(r) : "f"(lo), "f"(hi)); return r;
}
__device__ __forceinline__ void fma2(u64 &d, u64 a, u64 b) {
    asm("fma.rn.f32x2 %0,%1,%2,%0;" : "+l"(d) : "l"(a), "l"(b));
}
__device__ __forceinline__ u64 add2(u64 a, u64 b) {
    u64 r; asm("add.rn.f32x2 %0,%1,%2;" : "=l"(r) : "l"(a), "l"(b)); return r;
}
__device__ __forceinline__ void unpk2(u64 v, float &lo, float &hi) {
    asm("mov.b64 {%0,%1},%2;" : "=f"(lo), "=f"(hi) : "l"(v));
}

// tanh(x) = 1 - 2/(2^(2x*log2e)+1): FMUL+EX2+FADD+RCP+FFMA (err ~1e-7)
__device__ __forceinline__ float fast_tanh(float x) {
    float g = x * 2.885390081777927f;   // 2*log2(e)
    float e; asm("ex2.approx.f32 %0, %1;" : "=f"(e) : "f"(g));
    float d = e + 1.0f;
    float r; asm("rcp.approx.f32 %0, %1;" : "=f"(r) : "f"(d));
    return fmaf(-2.0f, r, 1.0f);
}

// 4 threads per batch element; id = lane&3 owns h[3*id .. 3*id+3) COMPLETELY
// (full 24-f input dot + full 12-k recurrent dot). No reduction shuffles;
// per step only a 12-shfl broadcast all-gather of h. x pairs come straight
// from LDG.128 (ulonglong2), h pairs packed once per step.
__global__ void __launch_bounds__(64)
rnn_fused_kernel(const float* __restrict__ x,
                 const float* __restrict__ W_ih, const float* __restrict__ b_ih,
                 const float* __restrict__ W_hh, const float* __restrict__ b_hh,
                 const float* __restrict__ W1,  const float* __restrict__ b1,
                 const float* __restrict__ W2,  const float* __restrict__ b2,
                 const float* __restrict__ W3,  const float* __restrict__ b3,
                 float* __restrict__ out)
{
    const int tid  = blockIdx.x * 64 + threadIdx.x;
    const int elem = tid >> 2;
    const int lane = threadIdx.x & 31;
    const int id   = lane & 3;
    const int base = lane & ~3;
    const unsigned FULL = 0xFFFFFFFFu;

    // ---- weights in registers, packed along f / k ----
    u64 Wih[3][12];   // [local h][f-pair]
    u64 Whh[3][6];    // [local h][k-pair]
    u64 biasp[3];
    #pragma unroll
    for (int hh = 0; hh < 3; hh++) {
        const int h = 3 * id + hh;
        #pragma unroll
        for (int fp = 0; fp < 12; fp++)
            Wih[hh][fp] = pk2(W_ih[h * F_ + 2 * fp], W_ih[h * F_ + 2 * fp + 1]);
        #pragma unroll
        for (int kp = 0; kp < 6; kp++)
            Whh[hh][kp] = pk2(W_hh[h * H_ + 2 * kp], W_hh[h * H_ + 2 * kp + 1]);
        biasp[hh] = pk2(b_ih[h] + b_hh[h], 0.0f);
    }

    const char* xrow = (const char*)(x + (size_t)elem * (T_ * F_));  // 96B rows

    u64 XA[12], XB[12];   // double-buffered x (one step each, 24 floats = 12 u64)
    {
        const ulonglong2* p0 = (const ulonglong2*)(xrow);
        const ulonglong2* p1 = (const ulonglong2*)(xrow + 96);
        #pragma unroll
        for (int j = 0; j < 6; j++) {
            ulonglong2 q0 = p0[j]; XA[2*j] = q0.x; XA[2*j+1] = q0.y;
            ulonglong2 q1 = p1[j]; XB[2*j] = q1.x; XB[2*j+1] = q1.y;
        }
    }

    u64 hpk[6];           // h packed along k (12 floats)
    #pragma unroll
    for (int p = 0; p < 6; p++) hpk[p] = 0ULL;
    float t0 = 0.f, t1 = 0.f, t2 = 0.f;

    #define RNN_BODY(BUF, TSTEP)                                               \
    {                                                                          \
        /* input projection (h-independent; overlaps prev step's tail) */      \
        u64 aA0 = biasp[0], aA1 = biasp[1], aA2 = biasp[2];                    \
        u64 aB0 = 0, aB1 = 0, aB2 = 0;                                         \
        _Pragma("unroll")                                                      \
        for (int fp = 0; fp < 6; fp++) {                                       \
            fma2(aA0, Wih[0][fp], BUF[fp]);                                    \
            fma2(aA1, Wih[1][fp], BUF[fp]);                                    \
            fma2(aA2, Wih[2][fp], BUF[fp]);                                    \
        }                                                                      \
        _Pragma("unroll")                                                      \
        for (int fp = 6; fp < 12; fp++) {                                      \
            fma2(aB0, Wih[0][fp], BUF[fp]);                                    \
            fma2(aB1, Wih[1][fp], BUF[fp]);                                    \
            fma2(aB2, Wih[2][fp], BUF[fp]);                                    \
        }                                                                      \
        /* refill this buffer with x[t+2] (consumed above; WAR via scoreboard) */ \
        {                                                                      \
            int tn = (TSTEP) + 2; if (tn > T_ - 1) tn = T_ - 1;                \
            const ulonglong2* pn = (const ulonglong2*)(xrow + (size_t)tn * 96);\
            _Pragma("unroll")                                                  \
            for (int j = 0; j < 6; j++) {                                      \
                ulonglong2 q = pn[j]; BUF[2*j] = q.x; BUF[2*j+1] = q.y;        \
            }                                                                  \
        }                                                                      \
        /* recurrent part (waits on hpk from previous step) */                 \
        _Pragma("unroll")                                                      \
        for (int kp = 0; kp < 3; kp++) {                                       \
            fma2(aA0, Whh[0][kp], hpk[kp]);                                    \
            fma2(aA1, Whh[1][kp], hpk[kp]);                                    \
            fma2(aA2, Whh[2][kp], hpk[kp]);                                    \
        }                                                                      \
        _Pragma("unroll")                                                      \
        for (int kp = 3; kp < 6; kp++) {                                       \
            fma2(aB0, Whh[0][kp], hpk[kp]);                                    \
            fma2(aB1, Whh[1][kp], hpk[kp]);                                    \
            fma2(aB2, Whh[2][kp], hpk[kp]);                                    \
        }                                                                      \
        /* merge halves, horizontal add, tanh */                               \
        float lo, hi;                                                          \
        u64 s0 = add2(aA0, aB0); unpk2(s0, lo, hi); t0 = fast_tanh(lo + hi);   \
        u64 s1 = add2(aA1, aB1); unpk2(s1, lo, hi); t1 = fast_tanh(lo + hi);   \
        u64 s2 = add2(aA2, aB2); unpk2(s2, lo, hi); t2 = fast_tanh(lo + hi);   \
        /* broadcast all-gather: h[j] from lane base+j/3, value t[j%3] */      \
        float g0  = __shfl_sync(FULL, t0, base + 0);                           \
        float g1  = __shfl_sync(FULL, t1, base + 0);                           \
        float g2  = __shfl_sync(FULL, t2, base + 0);                           \
        float g3  = __shfl_sync(FULL, t0, base + 1);                           \
        float g4  = __shfl_sync(FULL, t1, base + 1);                           \
        float g5  = __shfl_sync(FULL, t2, base + 1);                           \
        float g6  = __shfl_sync(FULL, t0, base + 2);                           \
        float g7  = __shfl_sync(FULL, t1, base + 2);                           \
        float g8  = __shfl_sync(FULL, t2, base + 2);                           \
        float g9  = __shfl_sync(FULL, t0, base + 3);                           \
        float g10 = __shfl_sync(FULL, t1, base + 3);                           \
        float g11 = __shfl_sync(FULL, t2, base + 3);                           \
        hpk[0] = pk2(g0,  g1);                                                 \
        hpk[1] = pk2(g2,  g3);                                                 \
        hpk[2] = pk2(g4,  g5);                                                 \
        hpk[3] = pk2(g6,  g7);                                                 \
        hpk[4] = pk2(g8,  g9);                                                 \
        hpk[5] = pk2(g10, g11);                                                \
    }

    for (int t = 0; t < T_; t += 2) {
        RNN_BODY(XA, t)
        RNN_BODY(XB, t + 1)
    }
    #undef RNN_BODY

    // ---- MLP head: hpk holds full h_T ----
    if (id == 0) {
        float hf[12];
        #pragma unroll
        for (int p = 0; p < 6; p++) unpk2(hpk[p], hf[2*p], hf[2*p+1]);

        float o1[12];
        #pragma unroll
        for (int i = 0; i < 12; i++) {
            float s = b1[i];
            #pragma unroll
            for (int j = 0; j < 12; j++) s = fmaf(W1[i * 12 + j], hf[j], s);
            o1[i] = fmaxf(s, 0.0f);
        }
        float o2[12];
        #pragma unroll
        for (int i = 0; i < 12; i++) {
            float s = b2[i];
            #pragma unroll
            for (int j = 0; j < 12; j++) s = fmaf(W2[i * 12 + j], o1[j], s);
            o2[i] = fmaxf(s, 0.0f);
        }
        float s = b3[0];
        #pragma unroll
        for (int j = 0; j < 12; j++) s = fmaf(W3[j], o2[j], s);
        out[elem] = s;
    }
}

extern "C" void kernel_launch(void* const* d_in, const int* in_sizes, int n_in,
                              void* d_out, int out_size)
{
    (void)in_sizes; (void)n_in; (void)out_size;
    const float* x    = (const float*)d_in[0];
    const float* W_ih = (const float*)d_in[1];
    const float* b_ih = (const float*)d_in[2];
    const float* W_hh = (const float*)d_in[3];
    const float* b_hh = (const float*)d_in[4];
    const float* W1   = (const float*)d_in[5];
    const float* b1   = (const float*)d_in[6];
    const float* W2   = (const float*)d_in[7];
    const float* b2   = (const float*)d_in[8];
    const float* W3   = (const float*)d_in[9];
    const float* b3   = (const float*)d_in[10];
    float* out = (float*)d_out;

    // 4 threads/element, 64-thread blocks for even SM distribution
    rnn_fused_kernel<<<512, 64>>>(x, W_ih, b_ih, W_hh, b_hh,
                                  W1, b1, W2, b2, W3, b3, out);
}